// round 13
// baseline (speedup 1.0000x reference)
#include <cuda_runtime.h>
#include <cstdint>

// ---------------------------------------------------------------------------
// HeavyCompressor round 13: v11 (KT=64, 2-stage all-cp.async ring, ldsm +
// tf32 mma) with software-pipelined fragments: double-buffered a/b register
// fragments hide the ldsm->mma latency chain inside each tile; the next
// stage's cp.async issues after the first fragment load (LSU decongestion).
//   CTA: 128 rows x 256 cols (c | z), 512 threads, warp tile 64x32.
//   A raw fp32 bits (HMMA tf32 reads top 19 bits), B rna-preconverted.
//   Stage rows = 64 words = 256B = 16 cells of 16B, cell ^= (row & 7).
// ---------------------------------------------------------------------------

constexpr int D_     = 2048;
constexpr int HD_    = 128;
constexpr int CTA_M  = 128;
constexpr int KT     = 64;
constexpr int NK     = D_ / KT;                 // 32
constexpr int A_BYTES = CTA_M * 256;            // 32 KB
constexpr int B_BYTES = 256 * 256;              // 64 KB
constexpr int STAGE_BYTES = A_BYTES + B_BYTES;  // 96 KB
constexpr int EPI_STR = 276;
constexpr int SMEM_BYTES = 2 * STAGE_BYTES;     // 196608 (> 138KB epilogue)

__device__ uint32_t g_wtf32[256 * 2048];        // rna-preconverted [wkv;wz]

__device__ __forceinline__ uint32_t f2tf(float f) {
    uint32_t r;
    asm("cvt.rna.tf32.f32 %0, %1;" : "=r"(r) : "f"(f));
    return r;
}
__device__ __forceinline__ uint32_t smem_u32(const void* p) {
    uint32_t a;
    asm("{ .reg .u64 t; cvta.to.shared.u64 t, %1; cvt.u32.u64 %0, t; }" : "=r"(a) : "l"(p));
    return a;
}
__device__ __forceinline__ void cp16(uint32_t dst, const void* src) {
    asm volatile("cp.async.cg.shared.global [%0], [%1], 16;" :: "r"(dst), "l"(src) : "memory");
}
__device__ __forceinline__ void ldsm4(uint32_t* r, uint32_t addr) {
    asm volatile("ldmatrix.sync.aligned.m8n8.x4.shared.b16 {%0,%1,%2,%3}, [%4];"
                 : "=r"(r[0]), "=r"(r[1]), "=r"(r[2]), "=r"(r[3]) : "r"(addr));
}
__device__ __forceinline__ void mma_tf32(float* c, uint32_t a0, uint32_t a1,
                                         uint32_t a2, uint32_t a3,
                                         uint32_t b0, uint32_t b1) {
    asm volatile(
        "mma.sync.aligned.m16n8k8.row.col.f32.tf32.tf32.f32 "
        "{%0,%1,%2,%3}, {%4,%5,%6,%7}, {%8,%9}, {%0,%1,%2,%3};"
        : "+f"(c[0]), "+f"(c[1]), "+f"(c[2]), "+f"(c[3])
        : "r"(a0), "r"(a1), "r"(a2), "r"(a3), "r"(b0), "r"(b1));
}

__global__ void convert_w(const float4* __restrict__ wkv, const float4* __restrict__ wz) {
    int i = blockIdx.x * blockDim.x + threadIdx.x;      // 0..131071 float4s
    int row = i >> 9, c4 = i & 511;
    float4 v = (row < 128) ? wkv[row * 512 + c4] : wz[(row - 128) * 512 + c4];
    ((uint4*)g_wtf32)[i] = make_uint4(f2tf(v.x), f2tf(v.y), f2tf(v.z), f2tf(v.w));
}

__global__ __launch_bounds__(512, 1)
void heavy_compressor_v13(const float* __restrict__ h,
                          const float* __restrict__ bias,
                          float* __restrict__ out,
                          int write_second, int out_half)
{
    extern __shared__ char smem[];
    const uint32_t sbase = smem_u32(smem);

    const int tid  = threadIdx.x;
    const int wid  = tid >> 5;
    const int lane = tid & 31;
    const int g    = lane >> 2;
    const int tg   = lane & 3;
    const int warp_m = wid & 1;            // 2 x 64 rows
    const int warp_n = wid >> 1;           // 8 x 32 cols
    const long long row0 = (long long)blockIdx.x * CTA_M;

    float acc[4][4][4];
#pragma unroll
    for (int mi = 0; mi < 4; ++mi)
#pragma unroll
        for (int ni = 0; ni < 4; ++ni)
#pragma unroll
            for (int j = 0; j < 4; ++j) acc[mi][ni][j] = 0.f;

    // ---- cp.async loaders (affine, validated in v11) ----
    const int atr = tid >> 4;                          // 0..31
    const int akc = tid & 15;
    const float* asrc0 = h + (row0 + atr) * D_ + akc * 4;
    const uint32_t adst0 = atr * 256 + ((akc ^ (atr & 7)) * 16);
    const uint32_t* bsrc0 = g_wtf32 + atr * 2048 + akc * 4;
    const uint32_t bdst0 = A_BYTES + adst0;

    auto cp_stage = [&](int s) {
        const uint32_t base = sbase + (s & 1) * STAGE_BYTES;
        const int k0 = s * KT;
        const float* as = asrc0 + k0;
        const uint32_t* bs = bsrc0 + k0;
#pragma unroll
        for (int i = 0; i < 4; ++i)
            cp16(base + adst0 + i * 8192, as + (long long)i * 32 * D_);
#pragma unroll
        for (int i = 0; i < 8; ++i)
            cp16(base + bdst0 + i * 8192, bs + i * 65536);
        asm volatile("cp.async.commit_group;" ::: "memory");
    };

    // ---- ldsm lane-constant pieces: off(ks) = P + ((ks ^ KSX) << 5) ----
    const int l7   = lane & 7;
    const int KSX  = l7 >> 1;
    const int row16  = (lane & 7) | (((lane >> 3) & 1) << 3);
    const int hiA    = lane >> 4;
    const int brow16 = (lane & 7) | ((lane >> 4) << 3);
    const int hiB    = (lane >> 3) & 1;
    const uint32_t PA = row16 * 256 + ((hiA ^ (l7 & 1)) * 16) + warp_m * 16384;
    const uint32_t PB = A_BYTES + brow16 * 256 + ((hiB ^ (l7 & 1)) * 16) + warp_n * 8192;

    // ---- prologue ----
    cp_stage(0);

    // ---- mainloop: one barrier per tile, fragments double-buffered ----
#pragma unroll 1
    for (int t = 0; t < NK; ++t) {
        asm volatile("cp.async.wait_group 0;" ::: "memory");
        __syncthreads();

        const uint32_t cs = sbase + (t & 1) * STAGE_BYTES;

        uint32_t a[2][4][4], b[2][2][4];
        {   // ks = 0 fragments into buffer 0
            const uint32_t kx0 = (uint32_t)((0 ^ KSX) << 5);
#pragma unroll
            for (int mi = 0; mi < 4; ++mi) ldsm4(a[0][mi], cs + PA + mi * 4096 + kx0);
#pragma unroll
            for (int np = 0; np < 2; ++np) ldsm4(b[0][np], cs + PB + np * 4096 + kx0);
        }

        if (t + 1 < NK) cp_stage(t + 1);   // after the critical ldsm burst

#pragma unroll
        for (int ks = 0; ks < 8; ++ks) {
            const int cur = ks & 1, nxt = cur ^ 1;
            if (ks < 7) {                  // prefetch ks+1 fragments
                const uint32_t kx = (uint32_t)(((ks + 1) ^ KSX) << 5);
#pragma unroll
                for (int mi = 0; mi < 4; ++mi) ldsm4(a[nxt][mi], cs + PA + mi * 4096 + kx);
#pragma unroll
                for (int np = 0; np < 2; ++np) ldsm4(b[nxt][np], cs + PB + np * 4096 + kx);
            }
#pragma unroll
            for (int mi = 0; mi < 4; ++mi)
#pragma unroll
                for (int ni = 0; ni < 4; ++ni)
                    mma_tf32(acc[mi][ni],
                             a[cur][mi][0], a[cur][mi][1], a[cur][mi][2], a[cur][mi][3],
                             b[cur][ni >> 1][(ni & 1) * 2], b[cur][ni >> 1][(ni & 1) * 2 + 1]);
        }
    }

    // ---- epilogue: accums -> smem, windowed softmax-compress ----
    float* epi = (float*)smem;
    __syncthreads();
#pragma unroll
    for (int mi = 0; mi < 4; ++mi)
#pragma unroll
        for (int ni = 0; ni < 4; ++ni) {
            int m0 = warp_m * 64 + mi * 16 + g;
            int n0 = warp_n * 32 + ni * 8 + 2 * tg;
            *(float2*)(epi + m0 * EPI_STR + n0)       = make_float2(acc[mi][ni][0], acc[mi][ni][1]);
            *(float2*)(epi + (m0 + 8) * EPI_STR + n0) = make_float2(acc[mi][ni][2], acc[mi][ni][3]);
        }
    __syncthreads();

    const int win = tid >> 5;            // 16 windows of 8 rows
    float zb[8][4], cc[8][4];
#pragma unroll
    for (int r = 0; r < 8; ++r) {
        const float* rp = epi + (win * 8 + r) * EPI_STR;
        float4 c4 = *(const float4*)(rp + lane * 4);
        float4 z4 = *(const float4*)(rp + HD_ + lane * 4);
        float4 b4 = *(const float4*)(bias + r * HD_ + lane * 4);
        cc[r][0] = c4.x; cc[r][1] = c4.y; cc[r][2] = c4.z; cc[r][3] = c4.w;
        zb[r][0] = z4.x + b4.x; zb[r][1] = z4.y + b4.y;
        zb[r][2] = z4.z + b4.z; zb[r][3] = z4.w + b4.w;
    }
    float res[4];
#pragma unroll
    for (int i = 0; i < 4; ++i) {
        float mx = zb[0][i];
#pragma unroll
        for (int r = 1; r < 8; ++r) mx = fmaxf(mx, zb[r][i]);
        float s = 0.f, a2 = 0.f;
#pragma unroll
        for (int r = 0; r < 8; ++r) {
            float e = __expf(zb[r][i] - mx);
            s += e;
            a2 = fmaf(e, cc[r][i], a2);
        }
        res[i] = a2 / s;
    }
    const long long w = (long long)blockIdx.x * 16 + win;
    float4 v = make_float4(res[0], res[1], res[2], res[3]);
    float* dst = out + w * HD_ + lane * 4;
    *(float4*)dst = v;
    if (write_second) *(float4*)(dst + out_half) = v;
}

extern "C" void kernel_launch(void* const* d_in, const int* in_sizes, int n_in,
                              void* d_out, int out_size)
{
    const float* h    = (const float*)d_in[0];
    const float* wkv  = (const float*)d_in[1];
    const float* wz   = (const float*)d_in[2];
    const float* bias = (const float*)d_in[3];

    const int rows = in_sizes[0] / D_;              // 32768
    const int base = (rows / 8) * HD_;              // 524288
    const int write_second = (out_size >= 2 * base) ? 1 : 0;

    convert_w<<<512, 256>>>((const float4*)wkv, (const float4*)wz);

    cudaFuncSetAttribute(heavy_compressor_v13,
                         cudaFuncAttributeMaxDynamicSharedMemorySize, SMEM_BYTES);
    heavy_compressor_v13<<<rows / CTA_M, 512, SMEM_BYTES>>>(
        h, bias, (float*)d_out, write_second, base);
}

// round 14
// speedup vs baseline: 1.0395x; 1.0395x over previous
#include <cuda_runtime.h>
#include <cstdint>

// ---------------------------------------------------------------------------
// HeavyCompressor round 14: v11 (KT=64, 2-stage all-cp.async ring, ldsm +
// tf32 mma) with REGISTER-BUDGETED intra-tile pipelining:
//   - B fragments double-buffered across ks (+8 regs)
//   - A fragments in a depth-2 ring across mi (+4 regs vs per-ks block)
//   => every ldsm is >=4 MMAs ahead of its consumer; est ~115 regs (no spill).
//   CTA: 128 rows x 256 cols (c | z), 512 threads, warp tile 64x32.
//   A raw fp32 bits (HMMA tf32 reads top 19 bits), B rna-preconverted.
//   Stage rows = 64 words = 256B = 16 cells of 16B, cell ^= (row & 7).
// ---------------------------------------------------------------------------

constexpr int D_     = 2048;
constexpr int HD_    = 128;
constexpr int CTA_M  = 128;
constexpr int KT     = 64;
constexpr int NK     = D_ / KT;                 // 32
constexpr int A_BYTES = CTA_M * 256;            // 32 KB
constexpr int B_BYTES = 256 * 256;              // 64 KB
constexpr int STAGE_BYTES = A_BYTES + B_BYTES;  // 96 KB
constexpr int EPI_STR = 276;
constexpr int SMEM_BYTES = 2 * STAGE_BYTES;     // 196608 (> 138KB epilogue)

__device__ uint32_t g_wtf32[256 * 2048];        // rna-preconverted [wkv;wz]

__device__ __forceinline__ uint32_t f2tf(float f) {
    uint32_t r;
    asm("cvt.rna.tf32.f32 %0, %1;" : "=r"(r) : "f"(f));
    return r;
}
__device__ __forceinline__ uint32_t smem_u32(const void* p) {
    uint32_t a;
    asm("{ .reg .u64 t; cvta.to.shared.u64 t, %1; cvt.u32.u64 %0, t; }" : "=r"(a) : "l"(p));
    return a;
}
__device__ __forceinline__ void cp16(uint32_t dst, const void* src) {
    asm volatile("cp.async.cg.shared.global [%0], [%1], 16;" :: "r"(dst), "l"(src) : "memory");
}
__device__ __forceinline__ void ldsm4(uint32_t* r, uint32_t addr) {
    asm volatile("ldmatrix.sync.aligned.m8n8.x4.shared.b16 {%0,%1,%2,%3}, [%4];"
                 : "=r"(r[0]), "=r"(r[1]), "=r"(r[2]), "=r"(r[3]) : "r"(addr));
}
__device__ __forceinline__ void mma_tf32(float* c, uint32_t a0, uint32_t a1,
                                         uint32_t a2, uint32_t a3,
                                         uint32_t b0, uint32_t b1) {
    asm volatile(
        "mma.sync.aligned.m16n8k8.row.col.f32.tf32.tf32.f32 "
        "{%0,%1,%2,%3}, {%4,%5,%6,%7}, {%8,%9}, {%0,%1,%2,%3};"
        : "+f"(c[0]), "+f"(c[1]), "+f"(c[2]), "+f"(c[3])
        : "r"(a0), "r"(a1), "r"(a2), "r"(a3), "r"(b0), "r"(b1));
}

__global__ void convert_w(const float4* __restrict__ wkv, const float4* __restrict__ wz) {
    int i = blockIdx.x * blockDim.x + threadIdx.x;      // 0..131071 float4s
    int row = i >> 9, c4 = i & 511;
    float4 v = (row < 128) ? wkv[row * 512 + c4] : wz[(row - 128) * 512 + c4];
    ((uint4*)g_wtf32)[i] = make_uint4(f2tf(v.x), f2tf(v.y), f2tf(v.z), f2tf(v.w));
}

__global__ __launch_bounds__(512, 1)
void heavy_compressor_v14(const float* __restrict__ h,
                          const float* __restrict__ bias,
                          float* __restrict__ out,
                          int write_second, int out_half)
{
    extern __shared__ char smem[];
    const uint32_t sbase = smem_u32(smem);

    const int tid  = threadIdx.x;
    const int wid  = tid >> 5;
    const int lane = tid & 31;
    const int g    = lane >> 2;
    const int tg   = lane & 3;
    const int warp_m = wid & 1;            // 2 x 64 rows
    const int warp_n = wid >> 1;           // 8 x 32 cols
    const long long row0 = (long long)blockIdx.x * CTA_M;

    float acc[4][4][4];
#pragma unroll
    for (int mi = 0; mi < 4; ++mi)
#pragma unroll
        for (int ni = 0; ni < 4; ++ni)
#pragma unroll
            for (int j = 0; j < 4; ++j) acc[mi][ni][j] = 0.f;

    // ---- cp.async loaders (affine, validated in v11) ----
    const int atr = tid >> 4;                          // 0..31
    const int akc = tid & 15;
    const float* asrc0 = h + (row0 + atr) * D_ + akc * 4;
    const uint32_t adst0 = atr * 256 + ((akc ^ (atr & 7)) * 16);
    const uint32_t* bsrc0 = g_wtf32 + atr * 2048 + akc * 4;
    const uint32_t bdst0 = A_BYTES + adst0;

    auto cp_stage = [&](int s) {
        const uint32_t base = sbase + (s & 1) * STAGE_BYTES;
        const int k0 = s * KT;
        const float* as = asrc0 + k0;
        const uint32_t* bs = bsrc0 + k0;
#pragma unroll
        for (int i = 0; i < 4; ++i)
            cp16(base + adst0 + i * 8192, as + (long long)i * 32 * D_);
#pragma unroll
        for (int i = 0; i < 8; ++i)
            cp16(base + bdst0 + i * 8192, bs + i * 65536);
        asm volatile("cp.async.commit_group;" ::: "memory");
    };

    // ---- ldsm lane-constant pieces: off(ks) = P + ((ks ^ KSX) << 5) ----
    const int l7   = lane & 7;
    const int KSX  = l7 >> 1;
    const int row16  = (lane & 7) | (((lane >> 3) & 1) << 3);
    const int hiA    = lane >> 4;
    const int brow16 = (lane & 7) | ((lane >> 4) << 3);
    const int hiB    = (lane >> 3) & 1;
    const uint32_t PA = row16 * 256 + ((hiA ^ (l7 & 1)) * 16) + warp_m * 16384;
    const uint32_t PB = A_BYTES + brow16 * 256 + ((hiB ^ (l7 & 1)) * 16) + warp_n * 8192;

    // ---- prologue ----
    cp_stage(0);

    // ---- mainloop: one barrier per tile; B dbl-buffered, A depth-2 ring ----
#pragma unroll 1
    for (int t = 0; t < NK; ++t) {
        asm volatile("cp.async.wait_group 0;" ::: "memory");
        __syncthreads();

        const uint32_t cs = sbase + (t & 1) * STAGE_BYTES;

        uint32_t a[2][4], b[2][2][4];
        {   // prime: ks=0 B frags + (ks=0, mi=0) A frag
            const uint32_t kx0 = (uint32_t)((0 ^ KSX) << 5);
            ldsm4(b[0][0], cs + PB + kx0);
            ldsm4(b[0][1], cs + PB + 4096 + kx0);
            ldsm4(a[0],    cs + PA + kx0);
        }

        if (t + 1 < NK) cp_stage(t + 1);

#pragma unroll
        for (int ks = 0; ks < 8; ++ks) {
            const int cb = ks & 1, nb = cb ^ 1;
            const uint32_t kx  = (uint32_t)((ks ^ KSX) << 5);
            const uint32_t kxn = (uint32_t)(((ks + 1) ^ KSX) << 5);
            if (ks < 7) {                   // prefetch ks+1 B frags
                ldsm4(b[nb][0], cs + PB + kxn);
                ldsm4(b[nb][1], cs + PB + 4096 + kxn);
            }
#pragma unroll
            for (int mi = 0; mi < 4; ++mi) {
                const int ca = mi & 1, na = ca ^ 1;
                if (mi < 3)                 // prefetch (ks, mi+1)
                    ldsm4(a[na], cs + PA + (mi + 1) * 4096 + kx);
                else if (ks < 7)            // prefetch (ks+1, 0)
                    ldsm4(a[na], cs + PA + kxn);
#pragma unroll
                for (int ni = 0; ni < 4; ++ni)
                    mma_tf32(acc[mi][ni],
                             a[ca][0], a[ca][1], a[ca][2], a[ca][3],
                             b[cb][ni >> 1][(ni & 1) * 2],
                             b[cb][ni >> 1][(ni & 1) * 2 + 1]);
            }
        }
    }

    // ---- epilogue: accums -> smem, windowed softmax-compress ----
    float* epi = (float*)smem;
    __syncthreads();
#pragma unroll
    for (int mi = 0; mi < 4; ++mi)
#pragma unroll
        for (int ni = 0; ni < 4; ++ni) {
            int m0 = warp_m * 64 + mi * 16 + g;
            int n0 = warp_n * 32 + ni * 8 + 2 * tg;
            *(float2*)(epi + m0 * EPI_STR + n0)       = make_float2(acc[mi][ni][0], acc[mi][ni][1]);
            *(float2*)(epi + (m0 + 8) * EPI_STR + n0) = make_float2(acc[mi][ni][2], acc[mi][ni][3]);
        }
    __syncthreads();

    const int win = tid >> 5;            // 16 windows of 8 rows
    float zb[8][4], cc[8][4];
#pragma unroll
    for (int r = 0; r < 8; ++r) {
        const float* rp = epi + (win * 8 + r) * EPI_STR;
        float4 c4 = *(const float4*)(rp + lane * 4);
        float4 z4 = *(const float4*)(rp + HD_ + lane * 4);
        float4 b4 = *(const float4*)(bias + r * HD_ + lane * 4);
        cc[r][0] = c4.x; cc[r][1] = c4.y; cc[r][2] = c4.z; cc[r][3] = c4.w;
        zb[r][0] = z4.x + b4.x; zb[r][1] = z4.y + b4.y;
        zb[r][2] = z4.z + b4.z; zb[r][3] = z4.w + b4.w;
    }
    float res[4];
#pragma unroll
    for (int i = 0; i < 4; ++i) {
        float mx = zb[0][i];
#pragma unroll
        for (int r = 1; r < 8; ++r) mx = fmaxf(mx, zb[r][i]);
        float s = 0.f, a2 = 0.f;
#pragma unroll
        for (int r = 0; r < 8; ++r) {
            float e = __expf(zb[r][i] - mx);
            s += e;
            a2 = fmaf(e, cc[r][i], a2);
        }
        res[i] = a2 / s;
    }
    const long long w = (long long)blockIdx.x * 16 + win;
    float4 v = make_float4(res[0], res[1], res[2], res[3]);
    float* dst = out + w * HD_ + lane * 4;
    *(float4*)dst = v;
    if (write_second) *(float4*)(dst + out_half) = v;
}

extern "C" void kernel_launch(void* const* d_in, const int* in_sizes, int n_in,
                              void* d_out, int out_size)
{
    const float* h    = (const float*)d_in[0];
    const float* wkv  = (const float*)d_in[1];
    const float* wz   = (const float*)d_in[2];
    const float* bias = (const float*)d_in[3];

    const int rows = in_sizes[0] / D_;              // 32768
    const int base = (rows / 8) * HD_;              // 524288
    const int write_second = (out_size >= 2 * base) ? 1 : 0;

    convert_w<<<512, 256>>>((const float4*)wkv, (const float4*)wz);

    cudaFuncSetAttribute(heavy_compressor_v14,
                         cudaFuncAttributeMaxDynamicSharedMemorySize, SMEM_BYTES);
    heavy_compressor_v14<<<rows / CTA_M, 512, SMEM_BYTES>>>(
        h, bias, (float*)d_out, write_second, base);
}

// round 15
// speedup vs baseline: 1.1023x; 1.0605x over previous
#include <cuda_runtime.h>
#include <cstdint>

// ---------------------------------------------------------------------------
// HeavyCompressor round 15: B fragments served directly from L2.
//   W = [wkv;wz] pre-packed (pack_w) into mma-fragment order:
//     g_wmma[ nb(8) ][ ksg(256) ][ chunk(2) ][ lane(32) ] : uint4
//     uint4 = { w[N0][kp], w[N0][kp+4], w[N1][kp], w[N1][kp+4] } (rna tf32)
//     N0 = nb*32 + chunk*16 + (lane>>2), N1 = N0+8, kp = ksg*8 + (lane&3)
//   Kernel: each lane ldg.128 x2 per ks (double-buffered, prefetch 1 ks
//   ahead, crossing tile barriers freely) -> B needs no smem/ldsm/cp.async.
//   A: cp.async ring (raw fp32 bits, 2-stage, 256B rows, cell ^= row&7) +
//   ldsm, as validated in v11.
//   CTA: 128 rows x 256 cols (c | z), 512 threads, warp tile 64x32.
// ---------------------------------------------------------------------------

constexpr int D_     = 2048;
constexpr int HD_    = 128;
constexpr int CTA_M  = 128;
constexpr int KT     = 64;
constexpr int NK     = D_ / KT;                 // 32
constexpr int NKSG   = D_ / 8;                  // 256 global k-steps
constexpr int A_BYTES = CTA_M * 256;            // 32 KB per stage
constexpr int EPI_STR = 276;
constexpr int SMEM_BYTES = CTA_M * EPI_STR * 4; // 141312 (> 2*A_BYTES ring)

__device__ uint4 g_wmma[8 * 256 * 2 * 32];      // 2 MB, fragment-ordered W

__device__ __forceinline__ uint32_t f2tf(float f) {
    uint32_t r;
    asm("cvt.rna.tf32.f32 %0, %1;" : "=r"(r) : "f"(f));
    return r;
}
__device__ __forceinline__ uint32_t smem_u32(const void* p) {
    uint32_t a;
    asm("{ .reg .u64 t; cvta.to.shared.u64 t, %1; cvt.u32.u64 %0, t; }" : "=r"(a) : "l"(p));
    return a;
}
__device__ __forceinline__ void cp16(uint32_t dst, const void* src) {
    asm volatile("cp.async.cg.shared.global [%0], [%1], 16;" :: "r"(dst), "l"(src) : "memory");
}
__device__ __forceinline__ void ldsm4(uint32_t* r, uint32_t addr) {
    asm volatile("ldmatrix.sync.aligned.m8n8.x4.shared.b16 {%0,%1,%2,%3}, [%4];"
                 : "=r"(r[0]), "=r"(r[1]), "=r"(r[2]), "=r"(r[3]) : "r"(addr));
}
__device__ __forceinline__ void mma_tf32(float* c, uint32_t a0, uint32_t a1,
                                         uint32_t a2, uint32_t a3,
                                         uint32_t b0, uint32_t b1) {
    asm volatile(
        "mma.sync.aligned.m16n8k8.row.col.f32.tf32.tf32.f32 "
        "{%0,%1,%2,%3}, {%4,%5,%6,%7}, {%8,%9}, {%0,%1,%2,%3};"
        : "+f"(c[0]), "+f"(c[1]), "+f"(c[2]), "+f"(c[3])
        : "r"(a0), "r"(a1), "r"(a2), "r"(a3), "r"(b0), "r"(b1));
}

// Pack W into per-lane mma-fragment order (one-time, ~2MB).
__global__ void pack_w(const float* __restrict__ wkv, const float* __restrict__ wz) {
    int idx  = blockIdx.x * blockDim.x + threadIdx.x;   // 0..131071
    int lane = idx & 31;
    int c    = (idx >> 5) & 1;
    int ksg  = (idx >> 6) & 255;
    int nb   = idx >> 14;
    int g = lane >> 2, tg = lane & 3;
    int N0 = nb * 32 + c * 16 + g;
    int N1 = N0 + 8;
    int kp = ksg * 8 + tg;
    const float* r0 = (N0 < 128) ? (wkv + N0 * D_) : (wz + (N0 - 128) * D_);
    const float* r1 = (N1 < 128) ? (wkv + N1 * D_) : (wz + (N1 - 128) * D_);
    g_wmma[idx] = make_uint4(f2tf(r0[kp]), f2tf(r0[kp + 4]),
                             f2tf(r1[kp]), f2tf(r1[kp + 4]));
}

__global__ __launch_bounds__(512, 1)
void heavy_compressor_v15(const float* __restrict__ h,
                          const float* __restrict__ bias,
                          float* __restrict__ out,
                          int write_second, int out_half)
{
    extern __shared__ char smem[];
    const uint32_t sbase = smem_u32(smem);

    const int tid  = threadIdx.x;
    const int wid  = tid >> 5;
    const int lane = tid & 31;
    const int g    = lane >> 2;
    const int tg   = lane & 3;
    const int warp_m = wid & 1;            // 2 x 64 rows
    const int warp_n = wid >> 1;           // 8 x 32 cols
    const long long row0 = (long long)blockIdx.x * CTA_M;

    float acc[4][4][4];
#pragma unroll
    for (int mi = 0; mi < 4; ++mi)
#pragma unroll
        for (int ni = 0; ni < 4; ++ni)
#pragma unroll
            for (int j = 0; j < 4; ++j) acc[mi][ni][j] = 0.f;

    // ---- A cp.async loader (raw fp32 bits; 4 x cp16/thread/stage) ----
    const int atr = tid >> 4;                          // 0..31
    const int akc = tid & 15;
    const float* asrc0 = h + (row0 + atr) * D_ + akc * 4;
    const uint32_t adst0 = atr * 256 + ((akc ^ (atr & 7)) * 16);

    auto cp_stage = [&](int s) {
        const uint32_t base = sbase + (s & 1) * A_BYTES;
        const float* as = asrc0 + s * KT;
#pragma unroll
        for (int i = 0; i < 4; ++i)
            cp16(base + adst0 + i * 8192, as + (long long)i * 32 * D_);
        asm volatile("cp.async.commit_group;" ::: "memory");
    };

    // ---- B L2 loader: 2 x LDG.128 per ks, fragment-ordered ----
    const uint4* gB = g_wmma + (warp_n * 256) * 64 + lane;     // +64 per ksg
    auto ldB = [&](int ksg, uint4* bb) {
        const uint4* p = gB + ksg * 64;
        bb[0] = __ldg(p);
        bb[1] = __ldg(p + 32);
    };

    // ---- A ldsm lane-constant pieces: off(ks) = PA + ((ks ^ KSX) << 5) ----
    const int l7   = lane & 7;
    const int KSX  = l7 >> 1;
    const int row16 = (lane & 7) | (((lane >> 3) & 1) << 3);
    const int hiA   = lane >> 4;
    const uint32_t PA = row16 * 256 + ((hiA ^ (l7 & 1)) * 16) + warp_m * 16384;

    // ---- prologue ----
    cp_stage(0);
    uint4 bb[2][2];                                    // [buf][chunk]
    ldB(0, bb[0]);

    // ---- mainloop ----
#pragma unroll 1
    for (int t = 0; t < NK; ++t) {
        asm volatile("cp.async.wait_group 0;" ::: "memory");
        __syncthreads();

        if (t + 1 < NK) cp_stage(t + 1);

        const uint32_t cs = sbase + (t & 1) * A_BYTES;
#pragma unroll
        for (int ks = 0; ks < 8; ++ks) {
            const int cur = ks & 1;
            const int ksg = t * 8 + ks;
            if (ksg + 1 < NKSG) ldB(ksg + 1, bb[cur ^ 1]);   // crosses barriers freely

            const uint32_t kx = (uint32_t)((ks ^ KSX) << 5);
            uint32_t a[4][4];
#pragma unroll
            for (int mi = 0; mi < 4; ++mi)
                ldsm4(a[mi], cs + PA + mi * 4096 + kx);

            const uint32_t* bp0 = (const uint32_t*)&bb[cur][0];
            const uint32_t* bp1 = (const uint32_t*)&bb[cur][1];
#pragma unroll
            for (int mi = 0; mi < 4; ++mi) {
                mma_tf32(acc[mi][0], a[mi][0], a[mi][1], a[mi][2], a[mi][3], bp0[0], bp0[1]);
                mma_tf32(acc[mi][1], a[mi][0], a[mi][1], a[mi][2], a[mi][3], bp0[2], bp0[3]);
                mma_tf32(acc[mi][2], a[mi][0], a[mi][1], a[mi][2], a[mi][3], bp1[0], bp1[1]);
                mma_tf32(acc[mi][3], a[mi][0], a[mi][1], a[mi][2], a[mi][3], bp1[2], bp1[3]);
            }
        }
    }

    // ---- epilogue: accums -> smem, windowed softmax-compress ----
    float* epi = (float*)smem;
    __syncthreads();
#pragma unroll
    for (int mi = 0; mi < 4; ++mi)
#pragma unroll
        for (int ni = 0; ni < 4; ++ni) {
            int m0 = warp_m * 64 + mi * 16 + g;
            int n0 = warp_n * 32 + ni * 8 + 2 * tg;
            *(float2*)(epi + m0 * EPI_STR + n0)       = make_float2(acc[mi][ni][0], acc[mi][ni][1]);
            *(float2*)(epi + (m0 + 8) * EPI_STR + n0) = make_float2(acc[mi][ni][2], acc[mi][ni][3]);
        }
    __syncthreads();

    const int win = tid >> 5;            // 16 windows of 8 rows
    float zb[8][4], cc[8][4];
#pragma unroll
    for (int r = 0; r < 8; ++r) {
        const float* rp = epi + (win * 8 + r) * EPI_STR;
        float4 c4 = *(const float4*)(rp + lane * 4);
        float4 z4 = *(const float4*)(rp + HD_ + lane * 4);
        float4 b4 = *(const float4*)(bias + r * HD_ + lane * 4);
        cc[r][0] = c4.x; cc[r][1] = c4.y; cc[r][2] = c4.z; cc[r][3] = c4.w;
        zb[r][0] = z4.x + b4.x; zb[r][1] = z4.y + b4.y;
        zb[r][2] = z4.z + b4.z; zb[r][3] = z4.w + b4.w;
    }
    float res[4];
#pragma unroll
    for (int i = 0; i < 4; ++i) {
        float mx = zb[0][i];
#pragma unroll
        for (int r = 1; r < 8; ++r) mx = fmaxf(mx, zb[r][i]);
        float s = 0.f, a2 = 0.f;
#pragma unroll
        for (int r = 0; r < 8; ++r) {
            float e = __expf(zb[r][i] - mx);
            s += e;
            a2 = fmaf(e, cc[r][i], a2);
        }
        res[i] = a2 / s;
    }
    const long long w = (long long)blockIdx.x * 16 + win;
    float4 v = make_float4(res[0], res[1], res[2], res[3]);
    float* dst = out + w * HD_ + lane * 4;
    *(float4*)dst = v;
    if (write_second) *(float4*)(dst + out_half) = v;
}

extern "C" void kernel_launch(void* const* d_in, const int* in_sizes, int n_in,
                              void* d_out, int out_size)
{
    const float* h    = (const float*)d_in[0];
    const float* wkv  = (const float*)d_in[1];
    const float* wz   = (const float*)d_in[2];
    const float* bias = (const float*)d_in[3];

    const int rows = in_sizes[0] / D_;              // 32768
    const int base = (rows / 8) * HD_;              // 524288
    const int write_second = (out_size >= 2 * base) ? 1 : 0;

    pack_w<<<512, 256>>>(wkv, wz);

    cudaFuncSetAttribute(heavy_compressor_v15,
                         cudaFuncAttributeMaxDynamicSharedMemorySize, SMEM_BYTES);
    heavy_compressor_v15<<<rows / CTA_M, 512, SMEM_BYTES>>>(
        h, bias, (float*)d_out, write_second, base);
}

// round 16
// speedup vs baseline: 1.1259x; 1.0214x over previous
#include <cuda_runtime.h>
#include <cstdint>

// ---------------------------------------------------------------------------
// HeavyCompressor round 16: v15 (B fragments from L2, A cp.async+ldsm)
// re-tiled for TWO co-resident CTAs per SM: CTA_M=64, 256 threads, occ 2.
// 8 warps, 1m x 8n (warp tile 64x32) -> B-L2 stays unique per warp_n;
// crossbar/tensor ratio identical to v15; the two CTAs' barriers are
// independent, so one CTA's MMAs hide the other's post-barrier ldsm burst.
//   A: raw fp32 bits via cp.async 2-stage ring (KT=64, 256B rows,
//      cell ^= row&7), ldsm fragments.
//   B: pack_w pre-packs [wkv;wz] into per-lane mma-fragment order (rna tf32);
//      2 x LDG.128 per ks, double-buffered, prefetch crosses barriers.
// ---------------------------------------------------------------------------

constexpr int D_     = 2048;
constexpr int HD_    = 128;
constexpr int CTA_M  = 64;
constexpr int KT     = 64;
constexpr int NK     = D_ / KT;                 // 32
constexpr int NKSG   = D_ / 8;                  // 256 global k-steps
constexpr int A_BYTES = CTA_M * 256;            // 16 KB per stage
constexpr int EPI_STR = 276;
constexpr int SMEM_BYTES = CTA_M * EPI_STR * 4; // 70656 (> 2*A_BYTES ring)

__device__ uint4 g_wmma[8 * 256 * 2 * 32];      // 2 MB, fragment-ordered W

__device__ __forceinline__ uint32_t f2tf(float f) {
    uint32_t r;
    asm("cvt.rna.tf32.f32 %0, %1;" : "=r"(r) : "f"(f));
    return r;
}
__device__ __forceinline__ uint32_t smem_u32(const void* p) {
    uint32_t a;
    asm("{ .reg .u64 t; cvta.to.shared.u64 t, %1; cvt.u32.u64 %0, t; }" : "=r"(a) : "l"(p));
    return a;
}
__device__ __forceinline__ void cp16(uint32_t dst, const void* src) {
    asm volatile("cp.async.cg.shared.global [%0], [%1], 16;" :: "r"(dst), "l"(src) : "memory");
}
__device__ __forceinline__ void ldsm4(uint32_t* r, uint32_t addr) {
    asm volatile("ldmatrix.sync.aligned.m8n8.x4.shared.b16 {%0,%1,%2,%3}, [%4];"
                 : "=r"(r[0]), "=r"(r[1]), "=r"(r[2]), "=r"(r[3]) : "r"(addr));
}
__device__ __forceinline__ void mma_tf32(float* c, uint32_t a0, uint32_t a1,
                                         uint32_t a2, uint32_t a3,
                                         uint32_t b0, uint32_t b1) {
    asm volatile(
        "mma.sync.aligned.m16n8k8.row.col.f32.tf32.tf32.f32 "
        "{%0,%1,%2,%3}, {%4,%5,%6,%7}, {%8,%9}, {%0,%1,%2,%3};"
        : "+f"(c[0]), "+f"(c[1]), "+f"(c[2]), "+f"(c[3])
        : "r"(a0), "r"(a1), "r"(a2), "r"(a3), "r"(b0), "r"(b1));
}

// Pack W into per-lane mma-fragment order (one-time, ~2MB).
__global__ void pack_w(const float* __restrict__ wkv, const float* __restrict__ wz) {
    int idx  = blockIdx.x * blockDim.x + threadIdx.x;   // 0..131071
    int lane = idx & 31;
    int c    = (idx >> 5) & 1;
    int ksg  = (idx >> 6) & 255;
    int nb   = idx >> 14;
    int g = lane >> 2, tg = lane & 3;
    int N0 = nb * 32 + c * 16 + g;
    int N1 = N0 + 8;
    int kp = ksg * 8 + tg;
    const float* r0 = (N0 < 128) ? (wkv + N0 * D_) : (wz + (N0 - 128) * D_);
    const float* r1 = (N1 < 128) ? (wkv + N1 * D_) : (wz + (N1 - 128) * D_);
    g_wmma[idx] = make_uint4(f2tf(r0[kp]), f2tf(r0[kp + 4]),
                             f2tf(r1[kp]), f2tf(r1[kp + 4]));
}

__global__ __launch_bounds__(256, 2)
void heavy_compressor_v16(const float* __restrict__ h,
                          const float* __restrict__ bias,
                          float* __restrict__ out,
                          int write_second, int out_half)
{
    extern __shared__ char smem[];
    const uint32_t sbase = smem_u32(smem);

    const int tid  = threadIdx.x;
    const int wid  = tid >> 5;              // warp_n: 8 x 32 cols (warp_m = 0)
    const int lane = tid & 31;
    const int g    = lane >> 2;
    const int tg   = lane & 3;
    const long long row0 = (long long)blockIdx.x * CTA_M;

    float acc[4][4][4];                     // [mi][ni][frag], warp tile 64x32
#pragma unroll
    for (int mi = 0; mi < 4; ++mi)
#pragma unroll
        for (int ni = 0; ni < 4; ++ni)
#pragma unroll
            for (int j = 0; j < 4; ++j) acc[mi][ni][j] = 0.f;

    // ---- A cp.async loader: 1024 cells/stage, 4 per thread (affine) ----
    // cell idx = i*256 + tid ; row = i*16 + (tid>>4) ; kc = tid & 15
    const int atr = tid >> 4;               // 0..15
    const int akc = tid & 15;
    const float* asrc0 = h + (row0 + atr) * D_ + akc * 4;
    const uint32_t adst0 = atr * 256 + ((akc ^ (atr & 7)) * 16);   // (16i & 7)=0

    auto cp_stage = [&](int s) {
        const uint32_t base = sbase + (s & 1) * A_BYTES;
        const float* as = asrc0 + s * KT;
#pragma unroll
        for (int i = 0; i < 4; ++i)
            cp16(base + adst0 + i * 4096, as + (long long)i * 16 * D_);
        asm volatile("cp.async.commit_group;" ::: "memory");
    };

    // ---- B L2 loader: 2 x LDG.128 per ks, fragment-ordered ----
    const uint4* gB = g_wmma + (wid * 256) * 64 + lane;    // +64 per ksg
    auto ldB = [&](int ksg, uint4* bb) {
        const uint4* p = gB + ksg * 64;
        bb[0] = __ldg(p);
        bb[1] = __ldg(p + 32);
    };

    // ---- A ldsm lane-constant pieces: off(ks) = PA + ((ks ^ KSX) << 5) ----
    const int l7   = lane & 7;
    const int KSX  = l7 >> 1;
    const int row16 = (lane & 7) | (((lane >> 3) & 1) << 3);
    const int hiA   = lane >> 4;
    const uint32_t PA = row16 * 256 + ((hiA ^ (l7 & 1)) * 16);

    // ---- prologue ----
    cp_stage(0);
    uint4 bb[2][2];                         // [buf][chunk]
    ldB(0, bb[0]);

    // ---- mainloop ----
#pragma unroll 1
    for (int t = 0; t < NK; ++t) {
        asm volatile("cp.async.wait_group 0;" ::: "memory");
        __syncthreads();

        if (t + 1 < NK) cp_stage(t + 1);

        const uint32_t cs = sbase + (t & 1) * A_BYTES;
#pragma unroll
        for (int ks = 0; ks < 8; ++ks) {
            const int cur = ks & 1;
            const int ksg = t * 8 + ks;
            if (ksg + 1 < NKSG) ldB(ksg + 1, bb[cur ^ 1]);  // crosses barriers

            const uint32_t kx = (uint32_t)((ks ^ KSX) << 5);
            uint32_t a[4][4];
#pragma unroll
            for (int mi = 0; mi < 4; ++mi)
                ldsm4(a[mi], cs + PA + mi * 4096 + kx);

            const uint32_t* bp0 = (const uint32_t*)&bb[cur][0];
            const uint32_t* bp1 = (const uint32_t*)&bb[cur][1];
#pragma unroll
            for (int mi = 0; mi < 4; ++mi) {
                mma_tf32(acc[mi][0], a[mi][0], a[mi][1], a[mi][2], a[mi][3], bp0[0], bp0[1]);
                mma_tf32(acc[mi][1], a[mi][0], a[mi][1], a[mi][2], a[mi][3], bp0[2], bp0[3]);
                mma_tf32(acc[mi][2], a[mi][0], a[mi][1], a[mi][2], a[mi][3], bp1[0], bp1[1]);
                mma_tf32(acc[mi][3], a[mi][0], a[mi][1], a[mi][2], a[mi][3], bp1[2], bp1[3]);
            }
        }
    }

    // ---- epilogue: accums -> smem, windowed softmax-compress ----
    float* epi = (float*)smem;
    __syncthreads();
#pragma unroll
    for (int mi = 0; mi < 4; ++mi)
#pragma unroll
        for (int ni = 0; ni < 4; ++ni) {
            int m0 = mi * 16 + g;
            int n0 = wid * 32 + ni * 8 + 2 * tg;
            *(float2*)(epi + m0 * EPI_STR + n0)       = make_float2(acc[mi][ni][0], acc[mi][ni][1]);
            *(float2*)(epi + (m0 + 8) * EPI_STR + n0) = make_float2(acc[mi][ni][2], acc[mi][ni][3]);
        }
    __syncthreads();

    const int win = tid >> 5;               // 8 windows of 8 rows
    float zb[8][4], cc[8][4];
#pragma unroll
    for (int r = 0; r < 8; ++r) {
        const float* rp = epi + (win * 8 + r) * EPI_STR;
        float4 c4 = *(const float4*)(rp + lane * 4);
        float4 z4 = *(const float4*)(rp + HD_ + lane * 4);
        float4 b4 = *(const float4*)(bias + r * HD_ + lane * 4);
        cc[r][0] = c4.x; cc[r][1] = c4.y; cc[r][2] = c4.z; cc[r][3] = c4.w;
        zb[r][0] = z4.x + b4.x; zb[r][1] = z4.y + b4.y;
        zb[r][2] = z4.z + b4.z; zb[r][3] = z4.w + b4.w;
    }
    float res[4];
#pragma unroll
    for (int i = 0; i < 4; ++i) {
        float mx = zb[0][i];
#pragma unroll
        for (int r = 1; r < 8; ++r) mx = fmaxf(mx, zb[r][i]);
        float s = 0.f, a2 = 0.f;
#pragma unroll
        for (int r = 0; r < 8; ++r) {
            float e = __expf(zb[r][i] - mx);
            s += e;
            a2 = fmaf(e, cc[r][i], a2);
        }
        res[i] = a2 / s;
    }
    const long long w = (long long)blockIdx.x * 8 + win;
    float4 v = make_float4(res[0], res[1], res[2], res[3]);
    float* dst = out + w * HD_ + lane * 4;
    *(float4*)dst = v;
    if (write_second) *(float4*)(dst + out_half) = v;
}

extern "C" void kernel_launch(void* const* d_in, const int* in_sizes, int n_in,
                              void* d_out, int out_size)
{
    const float* h    = (const float*)d_in[0];
    const float* wkv  = (const float*)d_in[1];
    const float* wz   = (const float*)d_in[2];
    const float* bias = (const float*)d_in[3];

    const int rows = in_sizes[0] / D_;              // 32768
    const int base = (rows / 8) * HD_;              // 524288
    const int write_second = (out_size >= 2 * base) ? 1 : 0;

    pack_w<<<512, 256>>>(wkv, wz);

    cudaFuncSetAttribute(heavy_compressor_v16,
                         cudaFuncAttributeMaxDynamicSharedMemorySize, SMEM_BYTES);
    heavy_compressor_v16<<<rows / CTA_M, 256, SMEM_BYTES>>>(
        h, bias, (float*)d_out, write_second, base);
}

// round 17
// speedup vs baseline: 1.1396x; 1.0122x over previous
#include <cuda_runtime.h>
#include <cstdint>

// ---------------------------------------------------------------------------
// HeavyCompressor round 17: v16 (occ-2, B-from-L2, A cp.async+ldsm) with
// KT=128 -> 16 barrier periods (was 32). CTA_M=64, 256 threads, 8 warps
// (1m x 8n, warp tile 64x32), 2-stage A ring (2 x 32 KB).
//   A: raw fp32 bits via cp.async (HMMA tf32 reads top 19 bits), rows of
//      512B = 32 cells of 16B, cell ^= (row & 7); ldsm fragments.
//   B: pack_w pre-packs [wkv;wz] into per-lane mma-fragment order (rna
//      tf32); 2 x LDG.128 per ks from L2, double-buffered across barriers.
// ---------------------------------------------------------------------------

constexpr int D_     = 2048;
constexpr int HD_    = 128;
constexpr int CTA_M  = 64;
constexpr int KT     = 128;
constexpr int NK     = D_ / KT;                 // 16
constexpr int NKSG   = D_ / 8;                  // 256 global k-steps
constexpr int A_BYTES = CTA_M * 512;            // 32 KB per stage
constexpr int EPI_STR = 276;
constexpr int SMEM_BYTES = CTA_M * EPI_STR * 4; // 70656 (> 2*A_BYTES ring)

__device__ uint4 g_wmma[8 * 256 * 2 * 32];      // 2 MB, fragment-ordered W

__device__ __forceinline__ uint32_t f2tf(float f) {
    uint32_t r;
    asm("cvt.rna.tf32.f32 %0, %1;" : "=r"(r) : "f"(f));
    return r;
}
__device__ __forceinline__ uint32_t smem_u32(const void* p) {
    uint32_t a;
    asm("{ .reg .u64 t; cvta.to.shared.u64 t, %1; cvt.u32.u64 %0, t; }" : "=r"(a) : "l"(p));
    return a;
}
__device__ __forceinline__ void cp16(uint32_t dst, const void* src) {
    asm volatile("cp.async.cg.shared.global [%0], [%1], 16;" :: "r"(dst), "l"(src) : "memory");
}
__device__ __forceinline__ void ldsm4(uint32_t* r, uint32_t addr) {
    asm volatile("ldmatrix.sync.aligned.m8n8.x4.shared.b16 {%0,%1,%2,%3}, [%4];"
                 : "=r"(r[0]), "=r"(r[1]), "=r"(r[2]), "=r"(r[3]) : "r"(addr));
}
__device__ __forceinline__ void mma_tf32(float* c, uint32_t a0, uint32_t a1,
                                         uint32_t a2, uint32_t a3,
                                         uint32_t b0, uint32_t b1) {
    asm volatile(
        "mma.sync.aligned.m16n8k8.row.col.f32.tf32.tf32.f32 "
        "{%0,%1,%2,%3}, {%4,%5,%6,%7}, {%8,%9}, {%0,%1,%2,%3};"
        : "+f"(c[0]), "+f"(c[1]), "+f"(c[2]), "+f"(c[3])
        : "r"(a0), "r"(a1), "r"(a2), "r"(a3), "r"(b0), "r"(b1));
}

// Pack W into per-lane mma-fragment order (one-time, ~2MB).
__global__ void pack_w(const float* __restrict__ wkv, const float* __restrict__ wz) {
    int idx  = blockIdx.x * blockDim.x + threadIdx.x;   // 0..131071
    int lane = idx & 31;
    int c    = (idx >> 5) & 1;
    int ksg  = (idx >> 6) & 255;
    int nb   = idx >> 14;
    int g = lane >> 2, tg = lane & 3;
    int N0 = nb * 32 + c * 16 + g;
    int N1 = N0 + 8;
    int kp = ksg * 8 + tg;
    const float* r0 = (N0 < 128) ? (wkv + N0 * D_) : (wz + (N0 - 128) * D_);
    const float* r1 = (N1 < 128) ? (wkv + N1 * D_) : (wz + (N1 - 128) * D_);
    g_wmma[idx] = make_uint4(f2tf(r0[kp]), f2tf(r0[kp + 4]),
                             f2tf(r1[kp]), f2tf(r1[kp + 4]));
}

__global__ __launch_bounds__(256, 2)
void heavy_compressor_v17(const float* __restrict__ h,
                          const float* __restrict__ bias,
                          float* __restrict__ out,
                          int write_second, int out_half)
{
    extern __shared__ char smem[];
    const uint32_t sbase = smem_u32(smem);

    const int tid  = threadIdx.x;
    const int wid  = tid >> 5;              // warp_n: 8 x 32 cols
    const int lane = tid & 31;
    const int g    = lane >> 2;
    const int tg   = lane & 3;
    const long long row0 = (long long)blockIdx.x * CTA_M;

    float acc[4][4][4];                     // warp tile 64x32
#pragma unroll
    for (int mi = 0; mi < 4; ++mi)
#pragma unroll
        for (int ni = 0; ni < 4; ++ni)
#pragma unroll
            for (int j = 0; j < 4; ++j) acc[mi][ni][j] = 0.f;

    // ---- A cp.async loader: 2048 cells/stage, 8 per thread (affine) ----
    // cell idx = i*256 + tid ; row = i*8 + (tid>>5) ; kc = tid & 31
    const int atr = tid >> 5;               // 0..7
    const int akc = tid & 31;
    const float* asrc0 = h + (row0 + atr) * D_ + akc * 4;
    const uint32_t adst0 = atr * 512 + ((akc ^ atr) * 16);   // (8i & 7) = 0

    auto cp_stage = [&](int s) {
        const uint32_t base = sbase + (s & 1) * A_BYTES;
        const float* as = asrc0 + s * KT;
#pragma unroll
        for (int i = 0; i < 8; ++i)
            cp16(base + adst0 + i * 4096, as + (long long)i * 8 * D_);
        asm volatile("cp.async.commit_group;" ::: "memory");
    };

    // ---- B L2 loader: 2 x LDG.128 per ks, fragment-ordered ----
    const uint4* gB = g_wmma + (wid * 256) * 64 + lane;    // +64 per ksg
    auto ldB = [&](int ksg, uint4* bb) {
        const uint4* p = gB + ksg * 64;
        bb[0] = __ldg(p);
        bb[1] = __ldg(p + 32);
    };

    // ---- A ldsm lane-constant pieces: off(ks) = PA + ((ks ^ KSX) << 5) ----
    const int l7   = lane & 7;
    const int KSX  = l7 >> 1;
    const int row16 = (lane & 7) | (((lane >> 3) & 1) << 3);
    const int hiA   = lane >> 4;
    const uint32_t PA = row16 * 512 + ((hiA ^ (l7 & 1)) * 16);

    // ---- prologue ----
    cp_stage(0);
    uint4 bb[2][2];                         // [buf][chunk]
    ldB(0, bb[0]);

    // ---- mainloop: 16 barrier periods ----
#pragma unroll 1
    for (int t = 0; t < NK; ++t) {
        asm volatile("cp.async.wait_group 0;" ::: "memory");
        __syncthreads();

        if (t + 1 < NK) cp_stage(t + 1);

        const uint32_t cs = sbase + (t & 1) * A_BYTES;
#pragma unroll
        for (int ks = 0; ks < 16; ++ks) {
            const int cur = ks & 1;
            const int ksg = t * 16 + ks;
            if (ksg + 1 < NKSG) ldB(ksg + 1, bb[cur ^ 1]);  // crosses barriers

            const uint32_t kx = (uint32_t)((ks ^ KSX) << 5);
            uint32_t a[4][4];
#pragma unroll
            for (int mi = 0; mi < 4; ++mi)
                ldsm4(a[mi], cs + PA + mi * 8192 + kx);

            const uint32_t* bp0 = (const uint32_t*)&bb[cur][0];
            const uint32_t* bp1 = (const uint32_t*)&bb[cur][1];
#pragma unroll
            for (int mi = 0; mi < 4; ++mi) {
                mma_tf32(acc[mi][0], a[mi][0], a[mi][1], a[mi][2], a[mi][3], bp0[0], bp0[1]);
                mma_tf32(acc[mi][1], a[mi][0], a[mi][1], a[mi][2], a[mi][3], bp0[2], bp0[3]);
                mma_tf32(acc[mi][2], a[mi][0], a[mi][1], a[mi][2], a[mi][3], bp1[0], bp1[1]);
                mma_tf32(acc[mi][3], a[mi][0], a[mi][1], a[mi][2], a[mi][3], bp1[2], bp1[3]);
            }
        }
    }

    // ---- epilogue: accums -> smem, windowed softmax-compress ----
    float* epi = (float*)smem;
    __syncthreads();
#pragma unroll
    for (int mi = 0; mi < 4; ++mi)
#pragma unroll
        for (int ni = 0; ni < 4; ++ni) {
            int m0 = mi * 16 + g;
            int n0 = wid * 32 + ni * 8 + 2 * tg;
            *(float2*)(epi + m0 * EPI_STR + n0)       = make_float2(acc[mi][ni][0], acc[mi][ni][1]);
            *(float2*)(epi + (m0 + 8) * EPI_STR + n0) = make_float2(acc[mi][ni][2], acc[mi][ni][3]);
        }
    __syncthreads();

    const int win = tid >> 5;               // 8 windows of 8 rows
    float zb[8][4], cc[8][4];
#pragma unroll
    for (int r = 0; r < 8; ++r) {
        const float* rp = epi + (win * 8 + r) * EPI_STR;
        float4 c4 = *(const float4*)(rp + lane * 4);
        float4 z4 = *(const float4*)(rp + HD_ + lane * 4);
        float4 b4 = *(const float4*)(bias + r * HD_ + lane * 4);
        cc[r][0] = c4.x; cc[r][1] = c4.y; cc[r][2] = c4.z; cc[r][3] = c4.w;
        zb[r][0] = z4.x + b4.x; zb[r][1] = z4.y + b4.y;
        zb[r][2] = z4.z + b4.z; zb[r][3] = z4.w + b4.w;
    }
    float res[4];
#pragma unroll
    for (int i = 0; i < 4; ++i) {
        float mx = zb[0][i];
#pragma unroll
        for (int r = 1; r < 8; ++r) mx = fmaxf(mx, zb[r][i]);
        float s = 0.f, a2 = 0.f;
#pragma unroll
        for (int r = 0; r < 8; ++r) {
            float e = __expf(zb[r][i] - mx);
            s += e;
            a2 = fmaf(e, cc[r][i], a2);
        }
        res[i] = a2 / s;
    }
    const long long w = (long long)blockIdx.x * 8 + win;
    float4 v = make_float4(res[0], res[1], res[2], res[3]);
    float* dst = out + w * HD_ + lane * 4;
    *(float4*)dst = v;
    if (write_second) *(float4*)(dst + out_half) = v;
}

extern "C" void kernel_launch(void* const* d_in, const int* in_sizes, int n_in,
                              void* d_out, int out_size)
{
    const float* h    = (const float*)d_in[0];
    const float* wkv  = (const float*)d_in[1];
    const float* wz   = (const float*)d_in[2];
    const float* bias = (const float*)d_in[3];

    const int rows = in_sizes[0] / D_;              // 32768
    const int base = (rows / 8) * HD_;              // 524288
    const int write_second = (out_size >= 2 * base) ? 1 : 0;

    pack_w<<<512, 256>>>(wkv, wz);

    cudaFuncSetAttribute(heavy_compressor_v17,
                         cudaFuncAttributeMaxDynamicSharedMemorySize, SMEM_BYTES);
    heavy_compressor_v17<<<rows / CTA_M, 256, SMEM_BYTES>>>(
        h, bias, (float*)d_out, write_second, base);
}